// round 6
// baseline (speedup 1.0000x reference)
#include <cuda_runtime.h>
#include <cuda_bf16.h>
#include <cuda_fp16.h>
#include <cstdint>

#define N_NODES 8192
#define FIN     512
#define FOUT    256
#define BKC     64                   // K-chunk (j per mainloop iter)
#define NCHUNK  (N_NODES / BKC)      // 128
#define NWORDS  (N_NODES / 32)       // 256 mask words per row

// ---------------------------------------------------------------------------
// Device scratch
// ---------------------------------------------------------------------------
__device__ float g_h[(size_t)N_NODES * FOUT];        // 8 MB   h = x@W
__device__ float g_s[2 * N_NODES];                   // s_src | s_dst
__device__ float g_smax;                             // max_j s_dst
__device__ __half g_hT_hi[(size_t)FOUT * N_NODES];   // 4 MB   h^T fp16 hi
__device__ __half g_hT_lo[(size_t)FOUT * N_NODES];   // 4 MB   h^T fp16 residual
__device__ uint32_t g_maskT[(size_t)NWORDS * N_NODES]; // 8 MB maskT[jw][i]

// mish(u) = u*(t^2+2t)/(t^2+2t+2), t=e^u
__device__ __forceinline__ float fast_mish(float u) {
    if (u > 30.f) return u;
    float t = __expf(u);
    float v = t * (t + 2.f);
    return u * __fdividef(v, v + 2.f);
}
__device__ __forceinline__ uint32_t smem_u32(const void* p) {
    uint32_t a;
    asm("{ .reg .u64 t; cvta.to.shared.u64 t, %1; cvt.u32.u64 %0, t; }" : "=r"(a) : "l"(p));
    return a;
}
#define SW128(x) ((x) ^ (((x) >> 3) & 0x70))

// ---- baseline-PTX tensor / async ops (compute_103-safe) --------------------
__device__ __forceinline__ void ldsm4(uint32_t* r, uint32_t addr) {
    asm volatile("ldmatrix.sync.aligned.m8n8.x4.shared.b16 {%0,%1,%2,%3}, [%4];"
                 : "=r"(r[0]), "=r"(r[1]), "=r"(r[2]), "=r"(r[3]) : "r"(addr));
}
__device__ __forceinline__ void mma_f16(float* d, const uint32_t* a,
                                        uint32_t b0, uint32_t b1) {
    asm volatile("mma.sync.aligned.m16n8k16.row.col.f32.f16.f16.f32 "
                 "{%0,%1,%2,%3}, {%4,%5,%6,%7}, {%8,%9}, {%0,%1,%2,%3};"
                 : "+f"(d[0]), "+f"(d[1]), "+f"(d[2]), "+f"(d[3])
                 : "r"(a[0]), "r"(a[1]), "r"(a[2]), "r"(a[3]), "r"(b0), "r"(b1));
}
__device__ __forceinline__ void cpa16(uint32_t s, const void* g) {
    asm volatile("cp.async.cg.shared.global [%0], [%1], 16;" :: "r"(s), "l"(g));
}
#define CPA_COMMIT() asm volatile("cp.async.commit_group;" ::: "memory")
#define CPA_WAIT1()  asm volatile("cp.async.wait_group 1;" ::: "memory")
#define CPA_WAIT0()  asm volatile("cp.async.wait_group 0;" ::: "memory")

// ---------------------------------------------------------------------------
// Kernel 1: h = x @ W  (FFMA SGEMM)
// ---------------------------------------------------------------------------
__global__ __launch_bounds__(256) void k_sgemm_xw(
    const float* __restrict__ X, const float* __restrict__ W)
{
    __shared__ float As[16][64];
    __shared__ float Bs[16][64];
    const int bn = blockIdx.x * 64, bm = blockIdx.y * 64;
    const int tid = threadIdx.x, tx = tid & 15, ty = tid >> 4;
    float acc[4][4];
#pragma unroll
    for (int r = 0; r < 4; r++)
#pragma unroll
        for (int c = 0; c < 4; c++) acc[r][c] = 0.f;
    for (int k0 = 0; k0 < FIN; k0 += 16) {
#pragma unroll
        for (int i = tid; i < 1024; i += 256) {
            int m = i >> 4, k = i & 15;
            As[k][m] = X[(size_t)(bm + m) * FIN + k0 + k];
        }
#pragma unroll
        for (int i = tid; i < 1024; i += 256) {
            int k = i >> 6, n = i & 63;
            Bs[k][n] = W[(size_t)(k0 + k) * FOUT + bn + n];
        }
        __syncthreads();
#pragma unroll
        for (int k = 0; k < 16; k++) {
            float4 a4 = *(const float4*)&As[k][ty * 4];
            float4 b4 = *(const float4*)&Bs[k][tx * 4];
            float a[4] = {a4.x, a4.y, a4.z, a4.w};
            float b[4] = {b4.x, b4.y, b4.z, b4.w};
#pragma unroll
            for (int r = 0; r < 4; r++)
#pragma unroll
                for (int c = 0; c < 4; c++) acc[r][c] = fmaf(a[r], b[c], acc[r][c]);
        }
        __syncthreads();
    }
#pragma unroll
    for (int r = 0; r < 4; r++) {
        float4 o = {acc[r][0], acc[r][1], acc[r][2], acc[r][3]};
        *(float4*)&g_h[(size_t)(bm + ty * 4 + r) * FOUT + bn + tx * 4] = o;
    }
}

// ---------------------------------------------------------------------------
// Kernel 2: s_src / s_dst
// ---------------------------------------------------------------------------
__global__ __launch_bounds__(256) void k_scores(const float* __restrict__ A)
{
    const int row = blockIdx.x * 8 + (threadIdx.x >> 5);
    const int lane = threadIdx.x & 31;
    const float4* h4 = (const float4*)(g_h + (size_t)row * FOUT);
    const float4* a14 = (const float4*)A;
    const float4* a24 = (const float4*)(A + FOUT);
    float s1 = 0.f, s2 = 0.f;
#pragma unroll
    for (int i = 0; i < 2; i++) {
        int idx = lane + i * 32;
        float4 h = h4[idx], a1 = a14[idx], a2 = a24[idx];
        s1 += h.x * a1.x + h.y * a1.y + h.z * a1.z + h.w * a1.w;
        s2 += h.x * a2.x + h.y * a2.y + h.z * a2.z + h.w * a2.w;
    }
#pragma unroll
    for (int off = 16; off; off >>= 1) {
        s1 += __shfl_down_sync(0xffffffffu, s1, off);
        s2 += __shfl_down_sync(0xffffffffu, s2, off);
    }
    if (lane == 0) { g_s[row] = s1; g_s[N_NODES + row] = s2; }
}

// ---------------------------------------------------------------------------
// Kernel 2b: global max of s_dst
// ---------------------------------------------------------------------------
__global__ __launch_bounds__(256) void k_smax()
{
    __shared__ float red[256];
    const int tid = threadIdx.x;
    float m = -1e30f;
    for (int i = tid; i < N_NODES; i += 256) m = fmaxf(m, g_s[N_NODES + i]);
    red[tid] = m;
    __syncthreads();
    for (int s = 128; s; s >>= 1) {
        if (tid < s) red[tid] = fmaxf(red[tid], red[tid + s]);
        __syncthreads();
    }
    if (tid == 0) g_smax = red[0];
}

// ---------------------------------------------------------------------------
// Kernel 3: h -> h^T split fp16 hi + lo
// ---------------------------------------------------------------------------
__global__ __launch_bounds__(256) void k_hsplit()
{
    __shared__ float t[32][33];
    const int tid = threadIdx.x, tx = tid & 31, ty = tid >> 5;
    const int ibase = blockIdx.x * 32, nbase = blockIdx.y * 32;
#pragma unroll
    for (int r = 0; r < 4; r++)
        t[ty + r * 8][tx] = g_h[(size_t)(ibase + ty + r * 8) * FOUT + nbase + tx];
    __syncthreads();
#pragma unroll
    for (int r = 0; r < 4; r++) {
        int nl = ty + r * 8;
        float v = t[tx][nl];
        __half hi = __float2half_rn(v);
        __half lo = __float2half_rn(v - __half2float(hi));
        size_t o = (size_t)(nbase + nl) * N_NODES + ibase + tx;
        g_hT_hi[o] = hi;
        g_hT_lo[o] = lo;
    }
}

// ---------------------------------------------------------------------------
// Kernel 3b: adj -> transposed bitmask  maskT[jw][i]
// ---------------------------------------------------------------------------
__global__ __launch_bounds__(256) void k_mask(const int* __restrict__ adj)
{
    __shared__ uint32_t sm[8][32];
    const int tid = threadIdx.x, lane = tid & 31, wid = tid >> 5;
    const int ibase = blockIdx.x * 32;
    const int jbase = blockIdx.y * 256;
#pragma unroll
    for (int rr = 0; rr < 4; rr++) {
        int il = wid * 4 + rr;
        const int* arow = adj + (size_t)(ibase + il) * N_NODES + jbase;
#pragma unroll
        for (int t = 0; t < 8; t++) {
            int av = arow[t * 32 + lane];
            uint32_t b = __ballot_sync(0xffffffffu, av > 0);
            if (lane == 0) sm[t][il] = b;
        }
    }
    __syncthreads();
    const int t = tid >> 5, il = tid & 31;
    g_maskT[(size_t)(jbase / 32 + t) * N_NODES + ibase + il] = sm[t][il];
}

// ---------------------------------------------------------------------------
// Kernel 4: fused attention, fp16 2-term, 3-stage pipeline.
// Grid 128 CTAs, 256 threads. CTA: M=64 rows, N=256, K=8192.
// Stage (72KB x3): A fp16 [64x64] 8K | B_hi [256x64] 32K | B_lo 32K
// Softmax shift: w' = exp(mish(s_i+s_j) - c_i), c_i = max(s_i + smax, 0) <= 1.
// Denominator accumulated from fp16-ROUNDED w' (num/den consistent).
// ---------------------------------------------------------------------------
#define ST_SZ 73728
#define OFF_BH 8192
#define OFF_BL 40960
#define ATTN_SMEM (3 * ST_SZ)   // 221184

__global__ __launch_bounds__(256, 1) void k_gat_attn(float* __restrict__ out)
{
    extern __shared__ char smem[];
    __shared__ float sden[4][64];
    __shared__ float denf[64];
    const uint32_t sb = smem_u32(smem);
    const int tid = threadIdx.x;
    const int lane = tid & 31;
    const int wid = tid >> 5;

    const int row0 = blockIdx.x * 64;

    // producer mapping: 4 threads per i-row, 16 j each
    const int r  = tid & 63;
    const int kg = tid >> 6;            // 0..3
    const float smax = g_smax;
    const float my_ssrc = g_s[row0 + r];
    const float ci = fmaxf(my_ssrc + smax, 0.f);
    const float* __restrict__ sdst = g_s + N_NODES;
    const char* __restrict__ hhi = (const char*)(g_hT_hi + (size_t)tid * N_NODES);
    const char* __restrict__ hlo = (const char*)(g_hT_lo + (size_t)tid * N_NODES);
    const uint32_t abase = (uint32_t)r * 128 + kg * 32;

    // consumer mapping: warp (wm, wn) owns 32x64 of the 64x256 tile
    const int wm = wid & 1;
    const int wn = wid >> 1;
    const int ksw = lane & 7;
    const int alsel = lane >> 4;
    const int bg = lane >> 3;
    const uint32_t arow = (uint32_t)(wm * 32 + (lane & 15)) * 128;

    float acc[2][8][4];
#pragma unroll
    for (int mt = 0; mt < 2; mt++)
#pragma unroll
        for (int nt = 0; nt < 8; nt++)
#pragma unroll
            for (int q = 0; q < 4; q++) acc[mt][nt][q] = 0.f;
    float psum = 0.f;

#define PROD_B(st_, c_)                                                          \
    {                                                                            \
        const size_t go = (size_t)(c_) * (BKC * 2);                              \
        const uint32_t db = (uint32_t)tid * 128;                                 \
        const uint32_t bh = sb + (st_) * ST_SZ + OFF_BH;                         \
        _Pragma("unroll")                                                        \
        for (int t = 0; t < 8; t++) {                                            \
            uint32_t so = SW128(db + t * 16);                                    \
            cpa16(bh + so, hhi + go + t * 16);                                   \
            cpa16(bh + 32768 + so, hlo + go + t * 16);                           \
        }                                                                        \
        CPA_COMMIT();                                                            \
    }

#define PROD_Q(st_, qt_, mw_, sp_)                                               \
    {                                                                            \
        float4 sv = __ldg((sp_) + (qt_));                                        \
        uint32_t mb = (mw_) >> ((qt_) * 4);                                      \
        float w0 = (mb & 1u) ? __expf(fast_mish(my_ssrc + sv.x) - ci) : 0.f;     \
        float w1 = (mb & 2u) ? __expf(fast_mish(my_ssrc + sv.y) - ci) : 0.f;     \
        float w2 = (mb & 4u) ? __expf(fast_mish(my_ssrc + sv.z) - ci) : 0.f;     \
        float w3 = (mb & 8u) ? __expf(fast_mish(my_ssrc + sv.w) - ci) : 0.f;     \
        __half2 p01 = __floats2half2_rn(w0, w1);                                 \
        __half2 p23 = __floats2half2_rn(w2, w3);                                 \
        float2 f01 = __half22float2(p01);                                        \
        float2 f23 = __half22float2(p23);                                        \
        psum += (f01.x + f01.y) + (f23.x + f23.y);                               \
        uint32_t u01 = *(uint32_t*)&p01, u23 = *(uint32_t*)&p23;                 \
        *(uint64_t*)(smem + (st_) * ST_SZ + SW128(abase + (qt_) * 8)) =          \
            (uint64_t)u01 | ((uint64_t)u23 << 32);                               \
    }

    // ---- prologue ----
    {
        PROD_B(0, 0);
        PROD_B(1, 1);
        const uint32_t word = g_maskT[(size_t)(kg >> 1) * N_NODES + row0 + r];
        const uint32_t mw = word >> ((kg & 1) * 16);
        const float4* sp = (const float4*)(sdst + kg * 16);
        PROD_Q(0, 0, mw, sp); PROD_Q(0, 1, mw, sp);
        PROD_Q(0, 2, mw, sp); PROD_Q(0, 3, mw, sp);
        CPA_WAIT1();
        __syncthreads();
    }

    for (int c = 0; c < NCHUNK; c++) {
        const int st = c % 3;
        const bool more = (c + 1 < NCHUNK);
        const uint32_t sbase = sb + st * ST_SZ;

        if (c + 2 < NCHUNK) PROD_B((c + 2) % 3, c + 2);

        uint32_t mw = 0;
        const float4* sp = nullptr;
        int ns = 0;
        if (more) {
            ns = (c + 1) % 3;
            const int j1 = (c + 1) * BKC + kg * 16;
            const uint32_t word = g_maskT[(size_t)(j1 >> 5) * N_NODES + row0 + r];
            mw = word >> ((kg & 1) * 16);
            sp = (const float4*)(sdst + j1);
        }

        // ---- consume 4 k16 slices, interleaving producer quarters ----
#pragma unroll
        for (int ks = 0; ks < 4; ks++) {
            uint32_t Af[2][4];
            const int kcA = ks * 2 + alsel;
#pragma unroll
            for (int mt = 0; mt < 2; mt++)
                ldsm4(Af[mt], sbase + arow + mt * 2048 + (uint32_t)((kcA ^ ksw) << 4));
#pragma unroll
            for (int ng = 0; ng < 4; ng++) {
                const int brow = wn * 64 + ng * 16 + (lane & 7) + ((bg & 2) << 2);
                const int kcB = ks * 2 + (bg & 1);
                uint32_t baddr = sbase + OFF_BH + (uint32_t)brow * 128 +
                                 (uint32_t)((kcB ^ ksw) << 4);
                uint32_t Bh[4], Bl[4];
                ldsm4(Bh, baddr);
                ldsm4(Bl, baddr + 32768);
                // dependent MMA pairs spaced 4 apart
                mma_f16(acc[0][ng * 2],     Af[0], Bh[0], Bh[1]);
                mma_f16(acc[0][ng * 2 + 1], Af[0], Bh[2], Bh[3]);
                mma_f16(acc[1][ng * 2],     Af[1], Bh[0], Bh[1]);
                mma_f16(acc[1][ng * 2 + 1], Af[1], Bh[2], Bh[3]);
                mma_f16(acc[0][ng * 2],     Af[0], Bl[0], Bl[1]);
                mma_f16(acc[0][ng * 2 + 1], Af[0], Bl[2], Bl[3]);
                mma_f16(acc[1][ng * 2],     Af[1], Bl[0], Bl[1]);
                mma_f16(acc[1][ng * 2 + 1], Af[1], Bl[2], Bl[3]);
            }
            if (more) PROD_Q(ns, ks, mw, sp);
        }

        if (c + 2 < NCHUNK) CPA_WAIT1(); else CPA_WAIT0();
        __syncthreads();
    }

    // ---- denominators (4 partials per row) ----
    sden[kg][r] = psum;
    __syncthreads();
    if (tid < 64)
        denf[tid] = (sden[0][tid] + sden[1][tid]) + (sden[2][tid] + sden[3][tid]);
    __syncthreads();

    // ---- epilogue: normalize + mish -> out ----
#pragma unroll
    for (int mt = 0; mt < 2; mt++) {
        const int lr = wm * 32 + mt * 16 + (lane >> 2);
        const float inv0 = __fdividef(1.f, denf[lr]);
        const float inv1 = __fdividef(1.f, denf[lr + 8]);
        float* o0 = out + (size_t)(row0 + lr) * FOUT;
        float* o1 = out + (size_t)(row0 + lr + 8) * FOUT;
#pragma unroll
        for (int nt = 0; nt < 8; nt++) {
            const int col = wn * 64 + nt * 8 + (lane & 3) * 2;
            float2 v0 = {fast_mish(acc[mt][nt][0] * inv0),
                         fast_mish(acc[mt][nt][1] * inv0)};
            float2 v1 = {fast_mish(acc[mt][nt][2] * inv1),
                         fast_mish(acc[mt][nt][3] * inv1)};
            *(float2*)&o0[col] = v0;
            *(float2*)&o1[col] = v1;
        }
    }
#undef PROD_B
#undef PROD_Q
}

// ---------------------------------------------------------------------------
extern "C" void kernel_launch(void* const* d_in, const int* in_sizes, int n_in,
                              void* d_out, int out_size)
{
    const float* x   = (const float*)d_in[0];   // [8192, 512]
    const int*   adj = (const int*)  d_in[1];   // [8192, 8192]
    const float* w   = (const float*)d_in[2];   // [512, 256]
    const float* a   = (const float*)d_in[3];   // [512, 1]
    float* out = (float*)d_out;                 // [8192, 256]

    cudaFuncSetAttribute(k_gat_attn, cudaFuncAttributeMaxDynamicSharedMemorySize,
                         ATTN_SMEM);

    k_mask<<<dim3(N_NODES / 32, N_NODES / 256), 256>>>(adj);
    k_sgemm_xw<<<dim3(FOUT / 64, N_NODES / 64), 256>>>(x, w);
    k_scores<<<N_NODES / 8, 256>>>(a);
    k_smax<<<1, 256>>>();
    k_hsplit<<<dim3(N_NODES / 32, FOUT / 32), 256>>>();
    k_gat_attn<<<128, 256, ATTN_SMEM>>>(out);
}

// round 7
// speedup vs baseline: 1.0445x; 1.0445x over previous
#include <cuda_runtime.h>
#include <cuda_bf16.h>
#include <cuda_fp16.h>
#include <cstdint>

#define N_NODES 8192
#define FIN     512
#define FOUT    256
#define BKC     64                   // K-chunk (j per mainloop iter)
#define NCHUNK  (N_NODES / BKC)      // 128
#define NWORDS  (N_NODES / 32)       // 256 mask words per row

// ---------------------------------------------------------------------------
// Device scratch
// ---------------------------------------------------------------------------
__device__ float g_h[(size_t)N_NODES * FOUT];        // 8 MB   h = x@W
__device__ float g_s[2 * N_NODES];                   // s_src | s_dst
__device__ float g_smax;                             // max_j s_dst
__device__ __half g_hT_hi[(size_t)FOUT * N_NODES];   // 4 MB   h^T fp16 hi
__device__ __half g_hT_lo[(size_t)FOUT * N_NODES];   // 4 MB   h^T fp16 residual
__device__ uint32_t g_maskT[(size_t)NWORDS * N_NODES]; // 8 MB maskT[jw][i]

// mish(u) = u*(t^2+2t)/(t^2+2t+2), t=e^u
__device__ __forceinline__ float fast_mish(float u) {
    if (u > 30.f) return u;
    float t = __expf(u);
    float v = t * (t + 2.f);
    return u * __fdividef(v, v + 2.f);
}
__device__ __forceinline__ uint32_t smem_u32(const void* p) {
    uint32_t a;
    asm("{ .reg .u64 t; cvta.to.shared.u64 t, %1; cvt.u32.u64 %0, t; }" : "=r"(a) : "l"(p));
    return a;
}
#define SW128(x) ((x) ^ (((x) >> 3) & 0x70))

// ---- baseline-PTX tensor / async ops (compute_103-safe) --------------------
__device__ __forceinline__ void ldsm4(uint32_t* r, uint32_t addr) {
    asm volatile("ldmatrix.sync.aligned.m8n8.x4.shared.b16 {%0,%1,%2,%3}, [%4];"
                 : "=r"(r[0]), "=r"(r[1]), "=r"(r[2]), "=r"(r[3]) : "r"(addr));
}
__device__ __forceinline__ void mma_f16(float* d, const uint32_t* a,
                                        uint32_t b0, uint32_t b1) {
    asm volatile("mma.sync.aligned.m16n8k16.row.col.f32.f16.f16.f32 "
                 "{%0,%1,%2,%3}, {%4,%5,%6,%7}, {%8,%9}, {%0,%1,%2,%3};"
                 : "+f"(d[0]), "+f"(d[1]), "+f"(d[2]), "+f"(d[3])
                 : "r"(a[0]), "r"(a[1]), "r"(a[2]), "r"(a[3]), "r"(b0), "r"(b1));
}
__device__ __forceinline__ void cpa16(uint32_t s, const void* g) {
    asm volatile("cp.async.cg.shared.global [%0], [%1], 16;" :: "r"(s), "l"(g));
}
#define CPA_COMMIT() asm volatile("cp.async.commit_group;" ::: "memory")
#define CPA_WAIT0()  asm volatile("cp.async.wait_group 0;" ::: "memory")

// ---------------------------------------------------------------------------
// Kernel 1: h = x @ W  (FFMA SGEMM)
// ---------------------------------------------------------------------------
__global__ __launch_bounds__(256) void k_sgemm_xw(
    const float* __restrict__ X, const float* __restrict__ W)
{
    __shared__ float As[16][64];
    __shared__ float Bs[16][64];
    const int bn = blockIdx.x * 64, bm = blockIdx.y * 64;
    const int tid = threadIdx.x, tx = tid & 15, ty = tid >> 4;
    float acc[4][4];
#pragma unroll
    for (int r = 0; r < 4; r++)
#pragma unroll
        for (int c = 0; c < 4; c++) acc[r][c] = 0.f;
    for (int k0 = 0; k0 < FIN; k0 += 16) {
#pragma unroll
        for (int i = tid; i < 1024; i += 256) {
            int m = i >> 4, k = i & 15;
            As[k][m] = X[(size_t)(bm + m) * FIN + k0 + k];
        }
#pragma unroll
        for (int i = tid; i < 1024; i += 256) {
            int k = i >> 6, n = i & 63;
            Bs[k][n] = W[(size_t)(k0 + k) * FOUT + bn + n];
        }
        __syncthreads();
#pragma unroll
        for (int k = 0; k < 16; k++) {
            float4 a4 = *(const float4*)&As[k][ty * 4];
            float4 b4 = *(const float4*)&Bs[k][tx * 4];
            float a[4] = {a4.x, a4.y, a4.z, a4.w};
            float b[4] = {b4.x, b4.y, b4.z, b4.w};
#pragma unroll
            for (int r = 0; r < 4; r++)
#pragma unroll
                for (int c = 0; c < 4; c++) acc[r][c] = fmaf(a[r], b[c], acc[r][c]);
        }
        __syncthreads();
    }
#pragma unroll
    for (int r = 0; r < 4; r++) {
        float4 o = {acc[r][0], acc[r][1], acc[r][2], acc[r][3]};
        *(float4*)&g_h[(size_t)(bm + ty * 4 + r) * FOUT + bn + tx * 4] = o;
    }
}

// ---------------------------------------------------------------------------
// Kernel 2: s_src / s_dst
// ---------------------------------------------------------------------------
__global__ __launch_bounds__(256) void k_scores(const float* __restrict__ A)
{
    const int row = blockIdx.x * 8 + (threadIdx.x >> 5);
    const int lane = threadIdx.x & 31;
    const float4* h4 = (const float4*)(g_h + (size_t)row * FOUT);
    const float4* a14 = (const float4*)A;
    const float4* a24 = (const float4*)(A + FOUT);
    float s1 = 0.f, s2 = 0.f;
#pragma unroll
    for (int i = 0; i < 2; i++) {
        int idx = lane + i * 32;
        float4 h = h4[idx], a1 = a14[idx], a2 = a24[idx];
        s1 += h.x * a1.x + h.y * a1.y + h.z * a1.z + h.w * a1.w;
        s2 += h.x * a2.x + h.y * a2.y + h.z * a2.z + h.w * a2.w;
    }
#pragma unroll
    for (int off = 16; off; off >>= 1) {
        s1 += __shfl_down_sync(0xffffffffu, s1, off);
        s2 += __shfl_down_sync(0xffffffffu, s2, off);
    }
    if (lane == 0) { g_s[row] = s1; g_s[N_NODES + row] = s2; }
}

// ---------------------------------------------------------------------------
// Kernel 2b: global max of s_dst
// ---------------------------------------------------------------------------
__global__ __launch_bounds__(256) void k_smax()
{
    __shared__ float red[256];
    const int tid = threadIdx.x;
    float m = -1e30f;
    for (int i = tid; i < N_NODES; i += 256) m = fmaxf(m, g_s[N_NODES + i]);
    red[tid] = m;
    __syncthreads();
    for (int s = 128; s; s >>= 1) {
        if (tid < s) red[tid] = fmaxf(red[tid], red[tid + s]);
        __syncthreads();
    }
    if (tid == 0) g_smax = red[0];
}

// ---------------------------------------------------------------------------
// Kernel 3: h -> h^T split fp16 hi + lo
// ---------------------------------------------------------------------------
__global__ __launch_bounds__(256) void k_hsplit()
{
    __shared__ float t[32][33];
    const int tid = threadIdx.x, tx = tid & 31, ty = tid >> 5;
    const int ibase = blockIdx.x * 32, nbase = blockIdx.y * 32;
#pragma unroll
    for (int r = 0; r < 4; r++)
        t[ty + r * 8][tx] = g_h[(size_t)(ibase + ty + r * 8) * FOUT + nbase + tx];
    __syncthreads();
#pragma unroll
    for (int r = 0; r < 4; r++) {
        int nl = ty + r * 8;
        float v = t[tx][nl];
        __half hi = __float2half_rn(v);
        __half lo = __float2half_rn(v - __half2float(hi));
        size_t o = (size_t)(nbase + nl) * N_NODES + ibase + tx;
        g_hT_hi[o] = hi;
        g_hT_lo[o] = lo;
    }
}

// ---------------------------------------------------------------------------
// Kernel 3b: adj -> transposed bitmask  maskT[jw][i]
// ---------------------------------------------------------------------------
__global__ __launch_bounds__(256) void k_mask(const int* __restrict__ adj)
{
    __shared__ uint32_t sm[8][32];
    const int tid = threadIdx.x, lane = tid & 31, wid = tid >> 5;
    const int ibase = blockIdx.x * 32;
    const int jbase = blockIdx.y * 256;
#pragma unroll
    for (int rr = 0; rr < 4; rr++) {
        int il = wid * 4 + rr;
        const int* arow = adj + (size_t)(ibase + il) * N_NODES + jbase;
#pragma unroll
        for (int t = 0; t < 8; t++) {
            int av = arow[t * 32 + lane];
            uint32_t b = __ballot_sync(0xffffffffu, av > 0);
            if (lane == 0) sm[t][il] = b;
        }
    }
    __syncthreads();
    const int t = tid >> 5, il = tid & 31;
    g_maskT[(size_t)(jbase / 32 + t) * N_NODES + ibase + il] = sm[t][il];
}

// ---------------------------------------------------------------------------
// Kernel 4: fused attention, fp16 2-term, N-split for 2 CTAs/SM.
// Grid (128, 2) = 256 CTAs, 256 thr. CTA: M=64 rows, N=128 cols, K=8192.
// Stage (40KB x2): A fp16 [64x64] 8K | B_hi [128x64] 16K | B_lo 16K
// Softmax shift: w' = exp(mish(s_i+s_j) - c_i), c_i = max(s_i + smax, 0).
// Denominator accumulated from fp16-ROUNDED w' (num/den consistent).
// ---------------------------------------------------------------------------
#define ST_SZ  40960
#define OFF_BH 8192
#define ATTN_SMEM (2 * ST_SZ)   // 81920 -> 2 CTAs/SM

__global__ __launch_bounds__(256, 2) void k_gat_attn(float* __restrict__ out)
{
    extern __shared__ char smem[];
    __shared__ float sden[4][64];
    __shared__ float denf[64];
    const uint32_t sb = smem_u32(smem);
    const int tid = threadIdx.x;
    const int lane = tid & 31;
    const int wid = tid >> 5;

    const int row0  = blockIdx.x * 64;
    const int nbase = blockIdx.y * 128;

    // producer mapping (A): 4 threads per i-row, 16 j each
    const int r  = tid & 63;
    const int kg = tid >> 6;            // 0..3
    const float my_ssrc = g_s[row0 + r];
    const float ci = fmaxf(my_ssrc + g_smax, 0.f);
    const float* __restrict__ sdst = g_s + N_NODES;
    const uint32_t abase = (uint32_t)r * 128 + kg * 32;

    // producer mapping (B): thread -> (local row, hi/lo component)
    const int brow_p = tid & 127;
    const int comp   = tid >> 7;
    const __half* bsel = comp ? g_hT_lo : g_hT_hi;
    const char* __restrict__ bsrc = (const char*)(bsel + (size_t)(nbase + brow_p) * N_NODES);
    const uint32_t bdst0 = OFF_BH + (uint32_t)comp * 16384;

    // consumer mapping: warp (wm, wn) owns 32x32 of the 64x128 tile
    const int wm = wid & 1;
    const int wn = wid >> 1;            // 0..3
    const int ksw = lane & 7;
    const int alsel = lane >> 4;
    const int bg = lane >> 3;
    const uint32_t arow = (uint32_t)(wm * 32 + (lane & 15)) * 128;

    float acc[2][4][4];
#pragma unroll
    for (int mt = 0; mt < 2; mt++)
#pragma unroll
        for (int nt = 0; nt < 4; nt++)
#pragma unroll
            for (int q = 0; q < 4; q++) acc[mt][nt][q] = 0.f;
    float psum = 0.f;

#define PROD_B(st_, c_)                                                          \
    {                                                                            \
        const char* src = bsrc + (size_t)(c_) * 128;                             \
        const uint32_t db = sb + (st_) * ST_SZ + bdst0;                          \
        const uint32_t rb = (uint32_t)brow_p * 128;                              \
        _Pragma("unroll")                                                        \
        for (int t = 0; t < 8; t++)                                              \
            cpa16(db + SW128(rb + t * 16), src + t * 16);                        \
        CPA_COMMIT();                                                            \
    }

#define PROD_Q(st_, qt_, mw_, sp_)                                               \
    {                                                                            \
        float4 sv = __ldg((sp_) + (qt_));                                        \
        uint32_t mb = (mw_) >> ((qt_) * 4);                                      \
        float w0 = (mb & 1u) ? __expf(fast_mish(my_ssrc + sv.x) - ci) : 0.f;     \
        float w1 = (mb & 2u) ? __expf(fast_mish(my_ssrc + sv.y) - ci) : 0.f;     \
        float w2 = (mb & 4u) ? __expf(fast_mish(my_ssrc + sv.z) - ci) : 0.f;     \
        float w3 = (mb & 8u) ? __expf(fast_mish(my_ssrc + sv.w) - ci) : 0.f;     \
        __half2 p01 = __floats2half2_rn(w0, w1);                                 \
        __half2 p23 = __floats2half2_rn(w2, w3);                                 \
        float2 f01 = __half22float2(p01);                                        \
        float2 f23 = __half22float2(p23);                                        \
        psum += (f01.x + f01.y) + (f23.x + f23.y);                               \
        uint32_t u01 = *(uint32_t*)&p01, u23 = *(uint32_t*)&p23;                 \
        *(uint64_t*)(smem + (st_) * ST_SZ + SW128(abase + (qt_) * 8)) =          \
            (uint64_t)u01 | ((uint64_t)u23 << 32);                               \
    }

    // ---- prologue: produce chunk 0 into stage 0 ----
    {
        PROD_B(0, 0);
        const uint32_t word = g_maskT[(size_t)(kg >> 1) * N_NODES + row0 + r];
        const uint32_t mw = word >> ((kg & 1) * 16);
        const float4* sp = (const float4*)(sdst + kg * 16);
        PROD_Q(0, 0, mw, sp); PROD_Q(0, 1, mw, sp);
        PROD_Q(0, 2, mw, sp); PROD_Q(0, 3, mw, sp);
        CPA_WAIT0();
        __syncthreads();
    }

    for (int c = 0; c < NCHUNK; c++) {
        const int st = c & 1, ns = st ^ 1;
        const bool more = (c + 1 < NCHUNK);
        const uint32_t sbase = sb + st * ST_SZ;

        uint32_t mw = 0;
        const float4* sp = nullptr;
        if (more) {
            PROD_B(ns, c + 1);
            const int j1 = (c + 1) * BKC + kg * 16;
            const uint32_t word = g_maskT[(size_t)(j1 >> 5) * N_NODES + row0 + r];
            mw = word >> ((kg & 1) * 16);
            sp = (const float4*)(sdst + j1);
        }

        // ---- consume 4 k16 slices, interleaving producer quarters ----
#pragma unroll
        for (int ks = 0; ks < 4; ks++) {
            uint32_t Af[2][4];
            const int kcA = ks * 2 + alsel;
#pragma unroll
            for (int mt = 0; mt < 2; mt++)
                ldsm4(Af[mt], sbase + arow + mt * 2048 + (uint32_t)((kcA ^ ksw) << 4));
#pragma unroll
            for (int ng = 0; ng < 2; ng++) {
                const int brow = wn * 32 + ng * 16 + (lane & 7) + ((bg & 2) << 2);
                const int kcB = ks * 2 + (bg & 1);
                uint32_t baddr = sbase + OFF_BH + (uint32_t)brow * 128 +
                                 (uint32_t)((kcB ^ ksw) << 4);
                uint32_t Bh[4], Bl[4];
                ldsm4(Bh, baddr);
                ldsm4(Bl, baddr + 16384);
                // dependent pairs (same acc) spaced 4 apart
                mma_f16(acc[0][ng * 2],     Af[0], Bh[0], Bh[1]);
                mma_f16(acc[0][ng * 2 + 1], Af[0], Bh[2], Bh[3]);
                mma_f16(acc[1][ng * 2],     Af[1], Bh[0], Bh[1]);
                mma_f16(acc[1][ng * 2 + 1], Af[1], Bh[2], Bh[3]);
                mma_f16(acc[0][ng * 2],     Af[0], Bl[0], Bl[1]);
                mma_f16(acc[0][ng * 2 + 1], Af[0], Bl[2], Bl[3]);
                mma_f16(acc[1][ng * 2],     Af[1], Bl[0], Bl[1]);
                mma_f16(acc[1][ng * 2 + 1], Af[1], Bl[2], Bl[3]);
            }
            if (more) PROD_Q(ns, ks, mw, sp);
        }

        CPA_WAIT0();
        __syncthreads();
    }

    // ---- denominators (4 partials per row; full K per CTA) ----
    sden[kg][r] = psum;
    __syncthreads();
    if (tid < 64)
        denf[tid] = (sden[0][tid] + sden[1][tid]) + (sden[2][tid] + sden[3][tid]);
    __syncthreads();

    // ---- epilogue: normalize + mish -> out (this CTA's N half) ----
#pragma unroll
    for (int mt = 0; mt < 2; mt++) {
        const int lr = wm * 32 + mt * 16 + (lane >> 2);
        const float inv0 = __fdividef(1.f, denf[lr]);
        const float inv1 = __fdividef(1.f, denf[lr + 8]);
        float* o0 = out + (size_t)(row0 + lr) * FOUT + nbase;
        float* o1 = out + (size_t)(row0 + lr + 8) * FOUT + nbase;
#pragma unroll
        for (int nt = 0; nt < 4; nt++) {
            const int col = wn * 32 + nt * 8 + (lane & 3) * 2;
            float2 v0 = {fast_mish(acc[mt][nt][0] * inv0),
                         fast_mish(acc[mt][nt][1] * inv0)};
            float2 v1 = {fast_mish(acc[mt][nt][2] * inv1),
                         fast_mish(acc[mt][nt][3] * inv1)};
            *(float2*)&o0[col] = v0;
            *(float2*)&o1[col] = v1;
        }
    }
#undef PROD_B
#undef PROD_Q
}

// ---------------------------------------------------------------------------
extern "C" void kernel_launch(void* const* d_in, const int* in_sizes, int n_in,
                              void* d_out, int out_size)
{
    const float* x   = (const float*)d_in[0];   // [8192, 512]
    const int*   adj = (const int*)  d_in[1];   // [8192, 8192]
    const float* w   = (const float*)d_in[2];   // [512, 256]
    const float* a   = (const float*)d_in[3];   // [512, 1]
    float* out = (float*)d_out;                 // [8192, 256]

    cudaFuncSetAttribute(k_gat_attn, cudaFuncAttributeMaxDynamicSharedMemorySize,
                         ATTN_SMEM);

    k_mask<<<dim3(N_NODES / 32, N_NODES / 256), 256>>>(adj);
    k_sgemm_xw<<<dim3(FOUT / 64, N_NODES / 64), 256>>>(x, w);
    k_scores<<<N_NODES / 8, 256>>>(a);
    k_smax<<<1, 256>>>();
    k_hsplit<<<dim3(N_NODES / 32, FOUT / 32), 256>>>();
    k_gat_attn<<<dim3(128, 2), 256, ATTN_SMEM>>>(out);
}

// round 8
// speedup vs baseline: 1.2807x; 1.2261x over previous
#include <cuda_runtime.h>
#include <cuda_bf16.h>
#include <cuda_fp16.h>
#include <cstdint>

#define N_NODES 8192
#define FIN     512
#define FOUT    256
#define BKC     64                   // K-chunk (j per mainloop iter)
#define NCHUNK  (N_NODES / BKC)      // 128
#define NWORDS  (N_NODES / 32)       // 256 mask words per row

// ---------------------------------------------------------------------------
// Device scratch
// ---------------------------------------------------------------------------
__device__ float g_h[(size_t)N_NODES * FOUT];        // 8 MB   h = x@W
__device__ float g_s[2 * N_NODES];                   // s_src | s_dst
__device__ float g_smax;                             // max_j s_dst
__device__ __half g_hT[(size_t)FOUT * N_NODES];      // 4 MB   h^T fp16
__device__ uint32_t g_maskT[(size_t)NWORDS * N_NODES]; // 8 MB maskT[jw][i]

// mish(u) = u*(t^2+2t)/(t^2+2t+2), t=e^u
__device__ __forceinline__ float fast_mish(float u) {
    if (u > 30.f) return u;
    float t = __expf(u);
    float v = t * (t + 2.f);
    return u * __fdividef(v, v + 2.f);
}
__device__ __forceinline__ uint32_t smem_u32(const void* p) {
    uint32_t a;
    asm("{ .reg .u64 t; cvta.to.shared.u64 t, %1; cvt.u32.u64 %0, t; }" : "=r"(a) : "l"(p));
    return a;
}
#define SW128(x) ((x) ^ (((x) >> 3) & 0x70))

// ---- baseline-PTX tensor / async ops (compute_103-safe) --------------------
__device__ __forceinline__ void ldsm4(uint32_t* r, uint32_t addr) {
    asm volatile("ldmatrix.sync.aligned.m8n8.x4.shared.b16 {%0,%1,%2,%3}, [%4];"
                 : "=r"(r[0]), "=r"(r[1]), "=r"(r[2]), "=r"(r[3]) : "r"(addr));
}
__device__ __forceinline__ void mma_f16(float* d, const uint32_t* a,
                                        uint32_t b0, uint32_t b1) {
    asm volatile("mma.sync.aligned.m16n8k16.row.col.f32.f16.f16.f32 "
                 "{%0,%1,%2,%3}, {%4,%5,%6,%7}, {%8,%9}, {%0,%1,%2,%3};"
                 : "+f"(d[0]), "+f"(d[1]), "+f"(d[2]), "+f"(d[3])
                 : "r"(a[0]), "r"(a[1]), "r"(a[2]), "r"(a[3]), "r"(b0), "r"(b1));
}
__device__ __forceinline__ void cpa16(uint32_t s, const void* g) {
    asm volatile("cp.async.cg.shared.global [%0], [%1], 16;" :: "r"(s), "l"(g));
}
#define CPA_COMMIT() asm volatile("cp.async.commit_group;" ::: "memory")
#define CPA_WAIT0()  asm volatile("cp.async.wait_group 0;" ::: "memory")

// ---------------------------------------------------------------------------
// Kernel 1: h = x @ W  (FFMA SGEMM)
// ---------------------------------------------------------------------------
__global__ __launch_bounds__(256) void k_sgemm_xw(
    const float* __restrict__ X, const float* __restrict__ W)
{
    __shared__ float As[16][64];
    __shared__ float Bs[16][64];
    const int bn = blockIdx.x * 64, bm = blockIdx.y * 64;
    const int tid = threadIdx.x, tx = tid & 15, ty = tid >> 4;
    float acc[4][4];
#pragma unroll
    for (int r = 0; r < 4; r++)
#pragma unroll
        for (int c = 0; c < 4; c++) acc[r][c] = 0.f;
    for (int k0 = 0; k0 < FIN; k0 += 16) {
#pragma unroll
        for (int i = tid; i < 1024; i += 256) {
            int m = i >> 4, k = i & 15;
            As[k][m] = X[(size_t)(bm + m) * FIN + k0 + k];
        }
#pragma unroll
        for (int i = tid; i < 1024; i += 256) {
            int k = i >> 6, n = i & 63;
            Bs[k][n] = W[(size_t)(k0 + k) * FOUT + bn + n];
        }
        __syncthreads();
#pragma unroll
        for (int k = 0; k < 16; k++) {
            float4 a4 = *(const float4*)&As[k][ty * 4];
            float4 b4 = *(const float4*)&Bs[k][tx * 4];
            float a[4] = {a4.x, a4.y, a4.z, a4.w};
            float b[4] = {b4.x, b4.y, b4.z, b4.w};
#pragma unroll
            for (int r = 0; r < 4; r++)
#pragma unroll
                for (int c = 0; c < 4; c++) acc[r][c] = fmaf(a[r], b[c], acc[r][c]);
        }
        __syncthreads();
    }
#pragma unroll
    for (int r = 0; r < 4; r++) {
        float4 o = {acc[r][0], acc[r][1], acc[r][2], acc[r][3]};
        *(float4*)&g_h[(size_t)(bm + ty * 4 + r) * FOUT + bn + tx * 4] = o;
    }
}

// ---------------------------------------------------------------------------
// Kernel 2: s_src / s_dst
// ---------------------------------------------------------------------------
__global__ __launch_bounds__(256) void k_scores(const float* __restrict__ A)
{
    const int row = blockIdx.x * 8 + (threadIdx.x >> 5);
    const int lane = threadIdx.x & 31;
    const float4* h4 = (const float4*)(g_h + (size_t)row * FOUT);
    const float4* a14 = (const float4*)A;
    const float4* a24 = (const float4*)(A + FOUT);
    float s1 = 0.f, s2 = 0.f;
#pragma unroll
    for (int i = 0; i < 2; i++) {
        int idx = lane + i * 32;
        float4 h = h4[idx], a1 = a14[idx], a2 = a24[idx];
        s1 += h.x * a1.x + h.y * a1.y + h.z * a1.z + h.w * a1.w;
        s2 += h.x * a2.x + h.y * a2.y + h.z * a2.z + h.w * a2.w;
    }
#pragma unroll
    for (int off = 16; off; off >>= 1) {
        s1 += __shfl_down_sync(0xffffffffu, s1, off);
        s2 += __shfl_down_sync(0xffffffffu, s2, off);
    }
    if (lane == 0) { g_s[row] = s1; g_s[N_NODES + row] = s2; }
}

// ---------------------------------------------------------------------------
// Kernel 2b: global max of s_dst
// ---------------------------------------------------------------------------
__global__ __launch_bounds__(256) void k_smax()
{
    __shared__ float red[256];
    const int tid = threadIdx.x;
    float m = -1e30f;
    for (int i = tid; i < N_NODES; i += 256) m = fmaxf(m, g_s[N_NODES + i]);
    red[tid] = m;
    __syncthreads();
    for (int s = 128; s; s >>= 1) {
        if (tid < s) red[tid] = fmaxf(red[tid], red[tid + s]);
        __syncthreads();
    }
    if (tid == 0) g_smax = red[0];
}

// ---------------------------------------------------------------------------
// Kernel 3: h -> h^T fp16
// ---------------------------------------------------------------------------
__global__ __launch_bounds__(256) void k_hsplit()
{
    __shared__ float t[32][33];
    const int tid = threadIdx.x, tx = tid & 31, ty = tid >> 5;
    const int ibase = blockIdx.x * 32, nbase = blockIdx.y * 32;
#pragma unroll
    for (int r = 0; r < 4; r++)
        t[ty + r * 8][tx] = g_h[(size_t)(ibase + ty + r * 8) * FOUT + nbase + tx];
    __syncthreads();
#pragma unroll
    for (int r = 0; r < 4; r++) {
        int nl = ty + r * 8;
        g_hT[(size_t)(nbase + nl) * N_NODES + ibase + tx] = __float2half_rn(t[tx][nl]);
    }
}

// ---------------------------------------------------------------------------
// Kernel 3b: adj -> transposed bitmask  maskT[jw][i]
// ---------------------------------------------------------------------------
__global__ __launch_bounds__(256) void k_mask(const int* __restrict__ adj)
{
    __shared__ uint32_t sm[8][32];
    const int tid = threadIdx.x, lane = tid & 31, wid = tid >> 5;
    const int ibase = blockIdx.x * 32;
    const int jbase = blockIdx.y * 256;
#pragma unroll
    for (int rr = 0; rr < 4; rr++) {
        int il = wid * 4 + rr;
        const int* arow = adj + (size_t)(ibase + il) * N_NODES + jbase;
#pragma unroll
        for (int t = 0; t < 8; t++) {
            int av = arow[t * 32 + lane];
            uint32_t b = __ballot_sync(0xffffffffu, av > 0);
            if (lane == 0) sm[t][il] = b;
        }
    }
    __syncthreads();
    const int t = tid >> 5, il = tid & 31;
    g_maskT[(size_t)(jbase / 32 + t) * N_NODES + ibase + il] = sm[t][il];
}

// ---------------------------------------------------------------------------
// Kernel 4: fused attention, single-term fp16, frag-pipelined.
// Grid (128, 2) = 256 CTAs, 256 thr. CTA: M=64 rows, N=128 cols, K=8192.
// Stage (24KB x2): A fp16 [64x64] 8K | B [128x64] 16K
// Softmax shift: w' = exp(mish(s_i+s_j) - c_i) in (0,1]; den from ROUNDED w'.
// Frag double-buffer: LDSM for slice ks+1 issued before MMAs of slice ks.
// ---------------------------------------------------------------------------
#define ST_SZ  24576
#define OFF_BH 8192
#define ATTN_SMEM (2 * ST_SZ)   // 49152 -> 2 CTAs/SM

__global__ __launch_bounds__(256, 2) void k_gat_attn(float* __restrict__ out)
{
    extern __shared__ char smem[];
    __shared__ float sden[4][64];
    __shared__ float denf[64];
    const uint32_t sb = smem_u32(smem);
    const int tid = threadIdx.x;
    const int lane = tid & 31;
    const int wid = tid >> 5;

    const int row0  = blockIdx.x * 64;
    const int nbase = blockIdx.y * 128;

    // producer mapping (A): 4 threads per i-row, 16 j each
    const int r  = tid & 63;
    const int kg = tid >> 6;            // 0..3
    const float my_ssrc = g_s[row0 + r];
    const float ci = fmaxf(my_ssrc + g_smax, 0.f);
    const float* __restrict__ sdst = g_s + N_NODES;
    const uint32_t abase = (uint32_t)r * 128 + kg * 32;

    // producer mapping (B): 2 threads per local n-row, 64B each
    const int brow_p = tid & 127;
    const int bhalf  = tid >> 7;
    const char* __restrict__ bsrc =
        (const char*)(g_hT + (size_t)(nbase + brow_p) * N_NODES) + bhalf * 64;
    const uint32_t brb = (uint32_t)brow_p * 128 + bhalf * 64;

    // consumer mapping: warp (wm, wn) owns 32x32 of the 64x128 tile
    const int wm = wid & 1;
    const int wn = wid >> 1;            // 0..3
    const int ksw = lane & 7;
    const int alsel = lane >> 4;
    const int bg = lane >> 3;
    const uint32_t arow = (uint32_t)(wm * 32 + (lane & 15)) * 128;
    // B row base addresses per ng (column term added per slice)
    const uint32_t brow0 = OFF_BH +
        (uint32_t)(wn * 32 + (lane & 7) + ((bg & 2) << 2)) * 128;
    const int kb0 = bg & 1;

    float acc[2][4][4];
#pragma unroll
    for (int mt = 0; mt < 2; mt++)
#pragma unroll
        for (int nt = 0; nt < 4; nt++)
#pragma unroll
            for (int q = 0; q < 4; q++) acc[mt][nt][q] = 0.f;
    float psum = 0.f;

    uint32_t Af[2][2][4];   // [buf][mt][4]
    uint32_t Bf[2][2][4];   // [buf][ng][4]

#define LOAD_FRAGS(base_, buf_, ks_)                                             \
    {                                                                            \
        const int kcA = (ks_) * 2 + alsel;                                       \
        ldsm4(Af[buf_][0], (base_) + arow + (uint32_t)((kcA ^ ksw) << 4));       \
        ldsm4(Af[buf_][1], (base_) + arow + 2048 + (uint32_t)((kcA ^ ksw) << 4));\
        const int kcB = (ks_) * 2 + kb0;                                         \
        ldsm4(Bf[buf_][0], (base_) + brow0 + (uint32_t)((kcB ^ ksw) << 4));      \
        ldsm4(Bf[buf_][1], (base_) + brow0 + 2048 + (uint32_t)((kcB ^ ksw) << 4));\
    }

#define PROD_B(st_, c_)                                                          \
    {                                                                            \
        const char* src = bsrc + (size_t)(c_) * 128;                             \
        const uint32_t db = sb + (st_) * ST_SZ + OFF_BH;                         \
        _Pragma("unroll")                                                        \
        for (int t = 0; t < 4; t++)                                              \
            cpa16(db + SW128(brb + t * 16), src + t * 16);                       \
        CPA_COMMIT();                                                            \
    }

#define PROD_Q(st_, qt_, mw_, sp_)                                               \
    {                                                                            \
        float4 sv = __ldg((sp_) + (qt_));                                        \
        uint32_t mb = (mw_) >> ((qt_) * 4);                                      \
        float w0 = (mb & 1u) ? __expf(fast_mish(my_ssrc + sv.x) - ci) : 0.f;     \
        float w1 = (mb & 2u) ? __expf(fast_mish(my_ssrc + sv.y) - ci) : 0.f;     \
        float w2 = (mb & 4u) ? __expf(fast_mish(my_ssrc + sv.z) - ci) : 0.f;     \
        float w3 = (mb & 8u) ? __expf(fast_mish(my_ssrc + sv.w) - ci) : 0.f;     \
        __half2 p01 = __floats2half2_rn(w0, w1);                                 \
        __half2 p23 = __floats2half2_rn(w2, w3);                                 \
        float2 f01 = __half22float2(p01);                                        \
        float2 f23 = __half22float2(p23);                                        \
        psum += (f01.x + f01.y) + (f23.x + f23.y);                               \
        uint32_t u01 = *(uint32_t*)&p01, u23 = *(uint32_t*)&p23;                 \
        *(uint64_t*)(smem + (st_) * ST_SZ + SW128(abase + (qt_) * 8)) =          \
            (uint64_t)u01 | ((uint64_t)u23 << 32);                               \
    }

    // ---- prologue: produce chunk 0 into stage 0 ----
    {
        PROD_B(0, 0);
        const uint32_t word = g_maskT[(size_t)(kg >> 1) * N_NODES + row0 + r];
        const uint32_t mw = word >> ((kg & 1) * 16);
        const float4* sp = (const float4*)(sdst + kg * 16);
        PROD_Q(0, 0, mw, sp); PROD_Q(0, 1, mw, sp);
        PROD_Q(0, 2, mw, sp); PROD_Q(0, 3, mw, sp);
        CPA_WAIT0();
        __syncthreads();
    }

    for (int c = 0; c < NCHUNK; c++) {
        const int st = c & 1, ns = st ^ 1;
        const bool more = (c + 1 < NCHUNK);
        const uint32_t sbase = sb + st * ST_SZ;

        uint32_t mw = 0;
        const float4* sp = nullptr;
        if (more) {
            PROD_B(ns, c + 1);
            const int j1 = (c + 1) * BKC + kg * 16;
            const uint32_t word = g_maskT[(size_t)(j1 >> 5) * N_NODES + row0 + r];
            mw = word >> ((kg & 1) * 16);
            sp = (const float4*)(sdst + j1);
        }

        // ---- frag-pipelined consume: 4 k16 slices ----
        LOAD_FRAGS(sbase, 0, 0);
#pragma unroll
        for (int ks = 0; ks < 4; ks++) {
            const int cur = ks & 1;
            if (ks < 3) LOAD_FRAGS(sbase, cur ^ 1, ks + 1);
            // 8 HMMAs, all-distinct accumulators (no RAW within slice)
            mma_f16(acc[0][0], Af[cur][0], Bf[cur][0][0], Bf[cur][0][1]);
            mma_f16(acc[0][1], Af[cur][0], Bf[cur][0][2], Bf[cur][0][3]);
            mma_f16(acc[1][0], Af[cur][1], Bf[cur][0][0], Bf[cur][0][1]);
            mma_f16(acc[1][1], Af[cur][1], Bf[cur][0][2], Bf[cur][0][3]);
            mma_f16(acc[0][2], Af[cur][0], Bf[cur][1][0], Bf[cur][1][1]);
            mma_f16(acc[0][3], Af[cur][0], Bf[cur][1][2], Bf[cur][1][3]);
            mma_f16(acc[1][2], Af[cur][1], Bf[cur][1][0], Bf[cur][1][1]);
            mma_f16(acc[1][3], Af[cur][1], Bf[cur][1][2], Bf[cur][1][3]);
            if (more) PROD_Q(ns, ks, mw, sp);
        }

        CPA_WAIT0();
        __syncthreads();
    }

    // ---- denominators (4 partials per row; full K per CTA) ----
    sden[kg][r] = psum;
    __syncthreads();
    if (tid < 64)
        denf[tid] = (sden[0][tid] + sden[1][tid]) + (sden[2][tid] + sden[3][tid]);
    __syncthreads();

    // ---- epilogue: normalize + mish -> out (this CTA's N half) ----
#pragma unroll
    for (int mt = 0; mt < 2; mt++) {
        const int lr = wm * 32 + mt * 16 + (lane >> 2);
        const float inv0 = __fdividef(1.f, denf[lr]);
        const float inv1 = __fdividef(1.f, denf[lr + 8]);
        float* o0 = out + (size_t)(row0 + lr) * FOUT + nbase;
        float* o1 = out + (size_t)(row0 + lr + 8) * FOUT + nbase;
#pragma unroll
        for (int nt = 0; nt < 4; nt++) {
            const int col = wn * 32 + nt * 8 + (lane & 3) * 2;
            float2 v0 = {fast_mish(acc[mt][nt][0] * inv0),
                         fast_mish(acc[mt][nt][1] * inv0)};
            float2 v1 = {fast_mish(acc[mt][nt][2] * inv1),
                         fast_mish(acc[mt][nt][3] * inv1)};
            *(float2*)&o0[col] = v0;
            *(float2*)&o1[col] = v1;
        }
    }
#undef LOAD_FRAGS
#undef PROD_B
#undef PROD_Q
}

// ---------------------------------------------------------------------------
extern "C" void kernel_launch(void* const* d_in, const int* in_sizes, int n_in,
                              void* d_out, int out_size)
{
    const float* x   = (const float*)d_in[0];   // [8192, 512]
    const int*   adj = (const int*)  d_in[1];   // [8192, 8192]
    const float* w   = (const float*)d_in[2];   // [512, 256]
    const float* a   = (const float*)d_in[3];   // [512, 1]
    float* out = (float*)d_out;                 // [8192, 256]

    cudaFuncSetAttribute(k_gat_attn, cudaFuncAttributeMaxDynamicSharedMemorySize,
                         ATTN_SMEM);

    k_mask<<<dim3(N_NODES / 32, N_NODES / 256), 256>>>(adj);
    k_sgemm_xw<<<dim3(FOUT / 64, N_NODES / 64), 256>>>(x, w);
    k_scores<<<N_NODES / 8, 256>>>(a);
    k_smax<<<1, 256>>>();
    k_hsplit<<<dim3(N_NODES / 32, FOUT / 32), 256>>>();
    k_gat_attn<<<dim3(128, 2), 256, ATTN_SMEM>>>(out);
}

// round 9
// speedup vs baseline: 1.3516x; 1.0554x over previous
#include <cuda_runtime.h>
#include <cuda_bf16.h>
#include <cuda_fp16.h>
#include <cstdint>

#define N_NODES 8192
#define FIN     512
#define FOUT    256
#define BKC     64                   // K-chunk (j per mainloop iter)
#define NCHUNK  (N_NODES / BKC)      // 128
#define NWORDS  (N_NODES / 32)       // 256 mask words per row

// ---------------------------------------------------------------------------
// Device scratch
// ---------------------------------------------------------------------------
__device__ float g_h[(size_t)N_NODES * FOUT];        // 8 MB   h = x@W
__device__ float g_s[2 * N_NODES];                   // s_src | s_dst
__device__ float g_smax;                             // max_j s_dst
__device__ __half g_hT[(size_t)FOUT * N_NODES];      // 4 MB   h^T fp16
__device__ uint32_t g_maskT[(size_t)NWORDS * N_NODES]; // 8 MB maskT[jw][i]

// mish(u) = u*(t^2+2t)/(t^2+2t+2), t=e^u
__device__ __forceinline__ float fast_mish(float u) {
    if (u > 30.f) return u;
    float t = __expf(u);
    float v = t * (t + 2.f);
    return u * __fdividef(v, v + 2.f);
}
__device__ __forceinline__ uint32_t smem_u32(const void* p) {
    uint32_t a;
    asm("{ .reg .u64 t; cvta.to.shared.u64 t, %1; cvt.u32.u64 %0, t; }" : "=r"(a) : "l"(p));
    return a;
}
#define SW128(x) ((x) ^ (((x) >> 3) & 0x70))

// ---- baseline-PTX tensor / async ops (compute_103-safe) --------------------
__device__ __forceinline__ void ldsm4(uint32_t* r, uint32_t addr) {
    asm volatile("ldmatrix.sync.aligned.m8n8.x4.shared.b16 {%0,%1,%2,%3}, [%4];"
                 : "=r"(r[0]), "=r"(r[1]), "=r"(r[2]), "=r"(r[3]) : "r"(addr));
}
__device__ __forceinline__ void mma_f16(float* d, const uint32_t* a,
                                        uint32_t b0, uint32_t b1) {
    asm volatile("mma.sync.aligned.m16n8k16.row.col.f32.f16.f16.f32 "
                 "{%0,%1,%2,%3}, {%4,%5,%6,%7}, {%8,%9}, {%0,%1,%2,%3};"
                 : "+f"(d[0]), "+f"(d[1]), "+f"(d[2]), "+f"(d[3])
                 : "r"(a[0]), "r"(a[1]), "r"(a[2]), "r"(a[3]), "r"(b0), "r"(b1));
}
__device__ __forceinline__ void cpa16(uint32_t s, const void* g) {
    asm volatile("cp.async.cg.shared.global [%0], [%1], 16;" :: "r"(s), "l"(g));
}
#define CPA_COMMIT() asm volatile("cp.async.commit_group;" ::: "memory")
#define CPA_WAIT0()  asm volatile("cp.async.wait_group 0;" ::: "memory")

// ---------------------------------------------------------------------------
// Kernel 1: h = x @ W  (FFMA SGEMM)
// ---------------------------------------------------------------------------
__global__ __launch_bounds__(256) void k_sgemm_xw(
    const float* __restrict__ X, const float* __restrict__ W)
{
    __shared__ float As[16][64];
    __shared__ float Bs[16][64];
    const int bn = blockIdx.x * 64, bm = blockIdx.y * 64;
    const int tid = threadIdx.x, tx = tid & 15, ty = tid >> 4;
    float acc[4][4];
#pragma unroll
    for (int r = 0; r < 4; r++)
#pragma unroll
        for (int c = 0; c < 4; c++) acc[r][c] = 0.f;
    for (int k0 = 0; k0 < FIN; k0 += 16) {
#pragma unroll
        for (int i = tid; i < 1024; i += 256) {
            int m = i >> 4, k = i & 15;
            As[k][m] = X[(size_t)(bm + m) * FIN + k0 + k];
        }
#pragma unroll
        for (int i = tid; i < 1024; i += 256) {
            int k = i >> 6, n = i & 63;
            Bs[k][n] = W[(size_t)(k0 + k) * FOUT + bn + n];
        }
        __syncthreads();
#pragma unroll
        for (int k = 0; k < 16; k++) {
            float4 a4 = *(const float4*)&As[k][ty * 4];
            float4 b4 = *(const float4*)&Bs[k][tx * 4];
            float a[4] = {a4.x, a4.y, a4.z, a4.w};
            float b[4] = {b4.x, b4.y, b4.z, b4.w};
#pragma unroll
            for (int r = 0; r < 4; r++)
#pragma unroll
                for (int c = 0; c < 4; c++) acc[r][c] = fmaf(a[r], b[c], acc[r][c]);
        }
        __syncthreads();
    }
#pragma unroll
    for (int r = 0; r < 4; r++) {
        float4 o = {acc[r][0], acc[r][1], acc[r][2], acc[r][3]};
        *(float4*)&g_h[(size_t)(bm + ty * 4 + r) * FOUT + bn + tx * 4] = o;
    }
}

// ---------------------------------------------------------------------------
// Kernel 2: s_src / s_dst
// ---------------------------------------------------------------------------
__global__ __launch_bounds__(256) void k_scores(const float* __restrict__ A)
{
    const int row = blockIdx.x * 8 + (threadIdx.x >> 5);
    const int lane = threadIdx.x & 31;
    const float4* h4 = (const float4*)(g_h + (size_t)row * FOUT);
    const float4* a14 = (const float4*)A;
    const float4* a24 = (const float4*)(A + FOUT);
    float s1 = 0.f, s2 = 0.f;
#pragma unroll
    for (int i = 0; i < 2; i++) {
        int idx = lane + i * 32;
        float4 h = h4[idx], a1 = a14[idx], a2 = a24[idx];
        s1 += h.x * a1.x + h.y * a1.y + h.z * a1.z + h.w * a1.w;
        s2 += h.x * a2.x + h.y * a2.y + h.z * a2.z + h.w * a2.w;
    }
#pragma unroll
    for (int off = 16; off; off >>= 1) {
        s1 += __shfl_down_sync(0xffffffffu, s1, off);
        s2 += __shfl_down_sync(0xffffffffu, s2, off);
    }
    if (lane == 0) { g_s[row] = s1; g_s[N_NODES + row] = s2; }
}

// ---------------------------------------------------------------------------
// Kernel 2b: global max of s_dst
// ---------------------------------------------------------------------------
__global__ __launch_bounds__(256) void k_smax()
{
    __shared__ float red[256];
    const int tid = threadIdx.x;
    float m = -1e30f;
    for (int i = tid; i < N_NODES; i += 256) m = fmaxf(m, g_s[N_NODES + i]);
    red[tid] = m;
    __syncthreads();
    for (int s = 128; s; s >>= 1) {
        if (tid < s) red[tid] = fmaxf(red[tid], red[tid + s]);
        __syncthreads();
    }
    if (tid == 0) g_smax = red[0];
}

// ---------------------------------------------------------------------------
// Kernel 3: h -> h^T fp16
// ---------------------------------------------------------------------------
__global__ __launch_bounds__(256) void k_hsplit()
{
    __shared__ float t[32][33];
    const int tid = threadIdx.x, tx = tid & 31, ty = tid >> 5;
    const int ibase = blockIdx.x * 32, nbase = blockIdx.y * 32;
#pragma unroll
    for (int r = 0; r < 4; r++)
        t[ty + r * 8][tx] = g_h[(size_t)(ibase + ty + r * 8) * FOUT + nbase + tx];
    __syncthreads();
#pragma unroll
    for (int r = 0; r < 4; r++) {
        int nl = ty + r * 8;
        g_hT[(size_t)(nbase + nl) * N_NODES + ibase + tx] = __float2half_rn(t[tx][nl]);
    }
}

// ---------------------------------------------------------------------------
// Kernel 3b: adj -> transposed bitmask  maskT[jw][i]
// ---------------------------------------------------------------------------
__global__ __launch_bounds__(256) void k_mask(const int* __restrict__ adj)
{
    __shared__ uint32_t sm[8][32];
    const int tid = threadIdx.x, lane = tid & 31, wid = tid >> 5;
    const int ibase = blockIdx.x * 32;
    const int jbase = blockIdx.y * 256;
#pragma unroll
    for (int rr = 0; rr < 4; rr++) {
        int il = wid * 4 + rr;
        const int* arow = adj + (size_t)(ibase + il) * N_NODES + jbase;
#pragma unroll
        for (int t = 0; t < 8; t++) {
            int av = arow[t * 32 + lane];
            uint32_t b = __ballot_sync(0xffffffffu, av > 0);
            if (lane == 0) sm[t][il] = b;
        }
    }
    __syncthreads();
    const int t = tid >> 5, il = tid & 31;
    g_maskT[(size_t)(jbase / 32 + t) * N_NODES + ibase + il] = sm[t][il];
}

// ---------------------------------------------------------------------------
// Kernel 4: fused attention, single-term fp16, frag-pipelined, NO w-gen dup.
// Grid 256 CTAs, 256 thr. CTA: M=32 rows, N=256 (full), K=8192.
// Stage (36KB x2): A fp16 [32x64] 4K | B [256x64] 32K  -> 2 CTAs/SM.
// Softmax shift: w' = exp(mish(s_i+s_j) - c_i) in (0,1]; den from ROUNDED w'.
// ---------------------------------------------------------------------------
#define ST_SZ  36864
#define OFF_B  4096
#define ATTN_SMEM (2 * ST_SZ)   // 73728 -> 2 CTAs/SM

__global__ __launch_bounds__(256, 2) void k_gat_attn(float* __restrict__ out)
{
    extern __shared__ char smem[];
    __shared__ float sden[8][32];
    __shared__ float denf[32];
    const uint32_t sb = smem_u32(smem);
    const int tid = threadIdx.x;
    const int lane = tid & 31;
    const int wid = tid >> 5;

    const int row0 = blockIdx.x * 32;

    // producer mapping (A): 8 threads per i-row, 8 j each
    const int r  = tid & 31;
    const int kg = tid >> 5;            // 0..7
    const float my_ssrc = g_s[row0 + r];
    const float ci = fmaxf(my_ssrc + g_smax, 0.f);
    const float* __restrict__ sdst = g_s + N_NODES;
    const uint32_t abase = (uint32_t)r * 128 + kg * 16;   // 8 j * 2B

    // producer mapping (B): 1 thread per n-row (256 rows), 128B per chunk
    const char* __restrict__ bsrc = (const char*)(g_hT + (size_t)tid * N_NODES);
    const uint32_t brb = (uint32_t)tid * 128;

    // consumer mapping: warp (wm, wn) owns 16x64 of the 32x256 tile
    const int wm = wid & 1;
    const int wn = wid >> 1;            // 0..3
    const int ksw = lane & 7;
    const int alsel = lane >> 4;
    const int bg = lane >> 3;
    const uint32_t arow = (uint32_t)(wm * 16 + (lane & 15)) * 128;
    const uint32_t brow0 = OFF_B +
        (uint32_t)(wn * 64 + (lane & 7) + ((bg & 2) << 2)) * 128;
    const int kb0 = bg & 1;

    float acc[8][4];
#pragma unroll
    for (int nt = 0; nt < 8; nt++)
#pragma unroll
        for (int q = 0; q < 4; q++) acc[nt][q] = 0.f;
    float psum = 0.f;

    uint32_t Af[2][4];      // [buf][4]
    uint32_t Bf[2][4][4];   // [buf][ng][4]

#define LOAD_FRAGS(base_, buf_, ks_)                                             \
    {                                                                            \
        const int kcA = (ks_) * 2 + alsel;                                       \
        ldsm4(Af[buf_], (base_) + arow + (uint32_t)((kcA ^ ksw) << 4));          \
        const int kcB = (ks_) * 2 + kb0;                                         \
        const uint32_t bo = (uint32_t)((kcB ^ ksw) << 4);                        \
        ldsm4(Bf[buf_][0], (base_) + brow0 + bo);                                \
        ldsm4(Bf[buf_][1], (base_) + brow0 + 2048 + bo);                         \
        ldsm4(Bf[buf_][2], (base_) + brow0 + 4096 + bo);                         \
        ldsm4(Bf[buf_][3], (base_) + brow0 + 6144 + bo);                         \
    }

#define PROD_B(st_, c_)                                                          \
    {                                                                            \
        const char* src = bsrc + (size_t)(c_) * 128;                             \
        const uint32_t db = sb + (st_) * ST_SZ + OFF_B;                          \
        _Pragma("unroll")                                                        \
        for (int t = 0; t < 8; t++)                                              \
            cpa16(db + SW128(brb + t * 16), src + t * 16);                       \
        CPA_COMMIT();                                                            \
    }

#define PROD_Q(st_, qt_, mw_, sp_)                                               \
    {                                                                            \
        float4 sv = __ldg((sp_) + (qt_));                                        \
        uint32_t mb = (mw_) >> ((qt_) * 4);                                      \
        float w0 = (mb & 1u) ? __expf(fast_mish(my_ssrc + sv.x) - ci) : 0.f;     \
        float w1 = (mb & 2u) ? __expf(fast_mish(my_ssrc + sv.y) - ci) : 0.f;     \
        float w2 = (mb & 4u) ? __expf(fast_mish(my_ssrc + sv.z) - ci) : 0.f;     \
        float w3 = (mb & 8u) ? __expf(fast_mish(my_ssrc + sv.w) - ci) : 0.f;     \
        __half2 p01 = __floats2half2_rn(w0, w1);                                 \
        __half2 p23 = __floats2half2_rn(w2, w3);                                 \
        float2 f01 = __half22float2(p01);                                        \
        float2 f23 = __half22float2(p23);                                        \
        psum += (f01.x + f01.y) + (f23.x + f23.y);                               \
        uint32_t u01 = *(uint32_t*)&p01, u23 = *(uint32_t*)&p23;                 \
        *(uint64_t*)(smem + (st_) * ST_SZ + SW128(abase + (qt_) * 8)) =          \
            (uint64_t)u01 | ((uint64_t)u23 << 32);                               \
    }

    // ---- prologue: produce chunk 0 into stage 0 ----
    {
        PROD_B(0, 0);
        const uint32_t word = g_maskT[(size_t)(kg >> 2) * N_NODES + row0 + r];
        const uint32_t mw = word >> ((kg & 3) * 8);
        const float4* sp = (const float4*)(sdst + kg * 8);
        PROD_Q(0, 0, mw, sp); PROD_Q(0, 1, mw, sp);
        CPA_WAIT0();
        __syncthreads();
    }

    for (int c = 0; c < NCHUNK; c++) {
        const int st = c & 1, ns = st ^ 1;
        const bool more = (c + 1 < NCHUNK);
        const uint32_t sbase = sb + st * ST_SZ;

        uint32_t mw = 0;
        const float4* sp = nullptr;
        if (more) {
            PROD_B(ns, c + 1);
            const int j1 = (c + 1) * BKC + kg * 8;
            const uint32_t word = g_maskT[(size_t)(j1 >> 5) * N_NODES + row0 + r];
            mw = word >> ((kg & 3) * 8);
            sp = (const float4*)(sdst + j1);
        }

        // ---- frag-pipelined consume: 4 k16 slices ----
        LOAD_FRAGS(sbase, 0, 0);
#pragma unroll
        for (int ks = 0; ks < 4; ks++) {
            const int cur = ks & 1;
            if (ks < 3) LOAD_FRAGS(sbase, cur ^ 1, ks + 1);
            // 8 HMMAs, all-distinct accumulators
            mma_f16(acc[0], Af[cur], Bf[cur][0][0], Bf[cur][0][1]);
            mma_f16(acc[1], Af[cur], Bf[cur][0][2], Bf[cur][0][3]);
            mma_f16(acc[2], Af[cur], Bf[cur][1][0], Bf[cur][1][1]);
            mma_f16(acc[3], Af[cur], Bf[cur][1][2], Bf[cur][1][3]);
            mma_f16(acc[4], Af[cur], Bf[cur][2][0], Bf[cur][2][1]);
            mma_f16(acc[5], Af[cur], Bf[cur][2][2], Bf[cur][2][3]);
            mma_f16(acc[6], Af[cur], Bf[cur][3][0], Bf[cur][3][1]);
            mma_f16(acc[7], Af[cur], Bf[cur][3][2], Bf[cur][3][3]);
            if (more && ks < 2) PROD_Q(ns, ks, mw, sp);
        }

        CPA_WAIT0();
        __syncthreads();
    }

    // ---- denominators (8 partials per row; full K per CTA) ----
    sden[kg][r] = psum;
    __syncthreads();
    if (tid < 32) {
        denf[tid] = ((sden[0][tid] + sden[1][tid]) + (sden[2][tid] + sden[3][tid])) +
                    ((sden[4][tid] + sden[5][tid]) + (sden[6][tid] + sden[7][tid]));
    }
    __syncthreads();

    // ---- epilogue: normalize + mish -> out (full 256-wide rows) ----
    {
        const int lr = wm * 16 + (lane >> 2);
        const float inv0 = __fdividef(1.f, denf[lr]);
        const float inv1 = __fdividef(1.f, denf[lr + 8]);
        float* o0 = out + (size_t)(row0 + lr) * FOUT;
        float* o1 = out + (size_t)(row0 + lr + 8) * FOUT;
#pragma unroll
        for (int nt = 0; nt < 8; nt++) {
            const int col = wn * 64 + nt * 8 + (lane & 3) * 2;
            float2 v0 = {fast_mish(acc[nt][0] * inv0),
                         fast_mish(acc[nt][1] * inv0)};
            float2 v1 = {fast_mish(acc[nt][2] * inv1),
                         fast_mish(acc[nt][3] * inv1)};
            *(float2*)&o0[col] = v0;
            *(float2*)&o1[col] = v1;
        }
    }
#undef LOAD_FRAGS
#undef PROD_B
#undef PROD_Q
}

// ---------------------------------------------------------------------------
extern "C" void kernel_launch(void* const* d_in, const int* in_sizes, int n_in,
                              void* d_out, int out_size)
{
    const float* x   = (const float*)d_in[0];   // [8192, 512]
    const int*   adj = (const int*)  d_in[1];   // [8192, 8192]
    const float* w   = (const float*)d_in[2];   // [512, 256]
    const float* a   = (const float*)d_in[3];   // [512, 1]
    float* out = (float*)d_out;                 // [8192, 256]

    cudaFuncSetAttribute(k_gat_attn, cudaFuncAttributeMaxDynamicSharedMemorySize,
                         ATTN_SMEM);

    k_mask<<<dim3(N_NODES / 32, N_NODES / 256), 256>>>(adj);
    k_sgemm_xw<<<dim3(FOUT / 64, N_NODES / 64), 256>>>(x, w);
    k_scores<<<N_NODES / 8, 256>>>(a);
    k_smax<<<1, 256>>>();
    k_hsplit<<<dim3(N_NODES / 32, FOUT / 32), 256>>>();
    k_gat_attn<<<256, 256, ATTN_SMEM>>>(out);
}